// round 2
// baseline (speedup 1.0000x reference)
#include <cuda_runtime.h>
#include <math.h>

// Problem constants (fixed shapes from reference)
#define B_   32
#define C_   256
#define H_   64
#define W_   64
#define HW_  (H_ * W_)          // 4096
#define BHW_ (B_ * HW_)         // 131072
#define EPS_ 1e-8f

#define THREADS_ 128
#define POS_PER_THREAD_ 2
#define NTHREADS_TOTAL_ (BHW_ / POS_PER_THREAD_)      // 65536
#define NBLOCKS_ (NTHREADS_TOTAL_ / THREADS_)         // 512

// Scratch accumulators: [0] = sum(sim*mask), [1] = sum(mask).
// Zero-initialized at module load; the finalizing block resets them to zero
// after each use, so every graph replay sees the same initial state.
__device__ float    g_acc[2];
__device__ unsigned g_count;

__global__ __launch_bounds__(THREADS_)
void cms_fused_kernel(const float* __restrict__ u,
                      const float* __restrict__ m,
                      const int*   __restrict__ mask,
                      float*       __restrict__ out) {
    const int tid = blockIdx.x * THREADS_ + threadIdx.x;     // 0..65535
    // This thread owns positions [2*tid, 2*tid+1]; both are in the same batch b
    // since HW_ (4096) is even.
    const int b   = tid >> 11;                 // (2*tid) / HW_
    const int hw  = (tid << 1) & (HW_ - 1);    // (2*tid) % HW_

    const float2* __restrict__ up = (const float2*)(u + (size_t)b * C_ * HW_ + hw);
    const float2* __restrict__ mp = (const float2*)(m + (size_t)b * C_ * HW_ + hw);

    float dot0 = 0.0f, uu0 = 0.0f, mm0 = 0.0f;
    float dot1 = 0.0f, uu1 = 0.0f, mm1 = 0.0f;

    #pragma unroll 8
    for (int c = 0; c < C_; ++c) {
        const float2 a = __ldg(up + (size_t)c * (HW_ / 2));
        const float2 x = __ldg(mp + (size_t)c * (HW_ / 2));
        dot0 = fmaf(a.x, x.x, dot0);
        uu0  = fmaf(a.x, a.x, uu0);
        mm0  = fmaf(x.x, x.x, mm0);
        dot1 = fmaf(a.y, x.y, dot1);
        uu1  = fmaf(a.y, a.y, uu1);
        mm1  = fmaf(x.y, x.y, mm1);
    }

    const int2 mk = __ldg((const int2*)(mask + (tid << 1)));
    const float mf0 = (mk.x != 0) ? 1.0f : 0.0f;
    const float mf1 = (mk.y != 0) ? 1.0f : 0.0f;

    const float d0 = fmaxf(sqrtf(uu0), EPS_) * fmaxf(sqrtf(mm0), EPS_);
    const float d1 = fmaxf(sqrtf(uu1), EPS_) * fmaxf(sqrtf(mm1), EPS_);

    float contrib = (dot0 / d0) * mf0 + (dot1 / d1) * mf1;
    float msum    = mf0 + mf1;

    // Warp reduction
    #pragma unroll
    for (int off = 16; off > 0; off >>= 1) {
        contrib += __shfl_down_sync(0xFFFFFFFFu, contrib, off);
        msum    += __shfl_down_sync(0xFFFFFFFFu, msum, off);
    }

    // Block reduction across 4 warps
    __shared__ float s_c[4];
    __shared__ float s_m[4];
    __shared__ bool  s_last;
    const int lane = threadIdx.x & 31;
    const int warp = threadIdx.x >> 5;
    if (lane == 0) { s_c[warp] = contrib; s_m[warp] = msum; }
    __syncthreads();
    if (warp == 0) {
        float bc = (lane < 4) ? s_c[lane] : 0.0f;
        float bm = (lane < 4) ? s_m[lane] : 0.0f;
        #pragma unroll
        for (int off = 2; off > 0; off >>= 1) {
            bc += __shfl_down_sync(0xFFFFFFFFu, bc, off);
            bm += __shfl_down_sync(0xFFFFFFFFu, bm, off);
        }
        if (lane == 0) {
            atomicAdd(&g_acc[0], bc);
            atomicAdd(&g_acc[1], bm);
            // Make this block's contribution visible before the count bump.
            __threadfence();
            const unsigned old = atomicAdd(&g_count, 1u);
            s_last = (old == (unsigned)(gridDim.x - 1));
        }
    }
    __syncthreads();

    // Last block to finish: produce the output and reset state for the next
    // graph replay.
    if (s_last && threadIdx.x == 0) {
        out[0] = g_acc[0] / g_acc[1];
        g_acc[0] = 0.0f;
        g_acc[1] = 0.0f;
        g_count  = 0u;
    }
}

extern "C" void kernel_launch(void* const* d_in, const int* in_sizes, int n_in,
                              void* d_out, int out_size) {
    const float* u    = (const float*)d_in[0];  // unmasked_latent_tensors [B,C,H,W]
    const float* m    = (const float*)d_in[1];  // masked_latent_tensors   [B,C,H,W]
    const int*   mask = (const int*)d_in[2];    // latent_mask [B,H,W]
    float* out = (float*)d_out;

    cms_fused_kernel<<<NBLOCKS_, THREADS_>>>(u, m, mask, out);
}

// round 3
// speedup vs baseline: 1.6656x; 1.6656x over previous
#include <cuda_runtime.h>
#include <math.h>

// Problem constants (fixed shapes from reference)
#define B_    32
#define C_    256
#define H_    64
#define W_    64
#define HW_   (H_ * W_)          // 4096
#define BHW_  (B_ * HW_)         // 131072
#define EPS_  1e-8f

#define THREADS_      256        // 128 positions x 2 channel-halves
#define POS_PER_BLK_  128
#define NBLOCKS_      (BHW_ / POS_PER_BLK_)   // 1024
#define CHALF_        (C_ / 2)   // 128 channels per thread

// Scratch accumulators: [0] = sum(sim*mask), [1] = sum(mask).
// Zero-initialized at module load; the finalizing block resets them after
// each use so every graph replay sees identical initial state.
__device__ float    g_acc[2];
__device__ unsigned g_count;

__global__ __launch_bounds__(THREADS_)
void cms_fused_kernel(const float* __restrict__ u,
                      const float* __restrict__ m,
                      const int*   __restrict__ mask,
                      float*       __restrict__ out) {
    const int pos_in_blk = threadIdx.x & (POS_PER_BLK_ - 1);  // 0..127
    const int half       = threadIdx.x >> 7;                  // 0 or 1
    const int pos        = blockIdx.x * POS_PER_BLK_ + pos_in_blk; // 0..131071

    const int b  = pos >> 12;            // / HW_
    const int hw = pos & (HW_ - 1);      // % HW_

    // This thread covers channels [half*128, half*128+128) of position (b,hw).
    const size_t base = (size_t)b * C_ * HW_ + (size_t)half * CHALF_ * HW_ + hw;
    const float* __restrict__ up = u + base;
    const float* __restrict__ mp = m + base;

    float dot = 0.0f, uu = 0.0f, mm = 0.0f;
    #pragma unroll 8
    for (int c = 0; c < CHALF_; ++c) {
        const float a = __ldg(up + (size_t)c * HW_);
        const float x = __ldg(mp + (size_t)c * HW_);
        dot = fmaf(a, x, dot);
        uu  = fmaf(a, a, uu);
        mm  = fmaf(x, x, mm);
    }

    // Combine the two channel-halves of each position through shared memory.
    __shared__ float s_dot[POS_PER_BLK_];
    __shared__ float s_uu[POS_PER_BLK_];
    __shared__ float s_mm[POS_PER_BLK_];
    __shared__ bool  s_last;

    if (half == 1) {
        s_dot[pos_in_blk] = dot;
        s_uu[pos_in_blk]  = uu;
        s_mm[pos_in_blk]  = mm;
    }
    __syncthreads();

    float contrib = 0.0f, msum = 0.0f;
    if (half == 0) {
        dot += s_dot[pos_in_blk];
        uu  += s_uu[pos_in_blk];
        mm  += s_mm[pos_in_blk];
        const float mf = (__ldg(mask + pos) != 0) ? 1.0f : 0.0f;
        const float denom = fmaxf(sqrtf(uu), EPS_) * fmaxf(sqrtf(mm), EPS_);
        contrib = (dot / denom) * mf;
        msum    = mf;
    }

    // Warp reduction (half==1 warps contribute zeros)
    #pragma unroll
    for (int off = 16; off > 0; off >>= 1) {
        contrib += __shfl_down_sync(0xFFFFFFFFu, contrib, off);
        msum    += __shfl_down_sync(0xFFFFFFFFu, msum, off);
    }

    // Block reduction across 8 warps (reuse s_dot/s_uu space after a sync)
    __syncthreads();
    const int lane = threadIdx.x & 31;
    const int warp = threadIdx.x >> 5;
    if (lane == 0) { s_dot[warp] = contrib; s_uu[warp] = msum; }
    __syncthreads();
    if (warp == 0) {
        float bc = (lane < 8) ? s_dot[lane] : 0.0f;
        float bm = (lane < 8) ? s_uu[lane] : 0.0f;
        #pragma unroll
        for (int off = 4; off > 0; off >>= 1) {
            bc += __shfl_down_sync(0xFFFFFFFFu, bc, off);
            bm += __shfl_down_sync(0xFFFFFFFFu, bm, off);
        }
        if (lane == 0) {
            atomicAdd(&g_acc[0], bc);
            atomicAdd(&g_acc[1], bm);
            __threadfence();
            const unsigned old = atomicAdd(&g_count, 1u);
            s_last = (old == (unsigned)(gridDim.x - 1));
        }
    }
    __syncthreads();

    // Last block: produce output and reset state for the next replay.
    if (s_last && threadIdx.x == 0) {
        out[0] = g_acc[0] / g_acc[1];
        g_acc[0] = 0.0f;
        g_acc[1] = 0.0f;
        g_count  = 0u;
    }
}

extern "C" void kernel_launch(void* const* d_in, const int* in_sizes, int n_in,
                              void* d_out, int out_size) {
    const float* u    = (const float*)d_in[0];  // unmasked_latent_tensors [B,C,H,W]
    const float* m    = (const float*)d_in[1];  // masked_latent_tensors   [B,C,H,W]
    const int*   mask = (const int*)d_in[2];    // latent_mask [B,H,W]
    float* out = (float*)d_out;

    cms_fused_kernel<<<NBLOCKS_, THREADS_>>>(u, m, mask, out);
}

// round 4
// speedup vs baseline: 1.7224x; 1.0341x over previous
#include <cuda_runtime.h>
#include <math.h>

// Problem constants (fixed shapes from reference)
#define B_    32
#define C_    256
#define H_    64
#define W_    64
#define HW_   (H_ * W_)          // 4096
#define BHW_  (B_ * HW_)         // 131072
#define EPS_  1e-8f

#define THREADS_      256        // 64 positions x 4 channel-quarters
#define POS_PER_BLK_  64
#define NBLOCKS_      (BHW_ / POS_PER_BLK_)   // 2048
#define NQUART_       4
#define CQ_           (C_ / NQUART_)          // 64 channels per thread

// Scratch accumulators: [0] = sum(sim*mask), [1] = sum(mask).
// Zero-initialized at module load; the finalizing block resets them after
// each use so every graph replay sees identical initial state.
__device__ float    g_acc[2];
__device__ unsigned g_count;

__global__ __launch_bounds__(THREADS_)
void cms_fused_kernel(const float* __restrict__ u,
                      const float* __restrict__ m,
                      const int*   __restrict__ mask,
                      float*       __restrict__ out) {
    const int pos_in_blk = threadIdx.x & (POS_PER_BLK_ - 1);  // 0..63
    const int quart      = threadIdx.x >> 6;                  // 0..3
    const int pos        = blockIdx.x * POS_PER_BLK_ + pos_in_blk; // 0..131071

    const int b  = pos >> 12;            // / HW_
    const int hw = pos & (HW_ - 1);      // % HW_

    // This thread covers channels [quart*64, quart*64+64) of position (b,hw).
    const size_t base = (size_t)b * C_ * HW_ + (size_t)quart * CQ_ * HW_ + hw;
    const float* __restrict__ up = u + base;
    const float* __restrict__ mp = m + base;

    float dot = 0.0f, uu = 0.0f, mm = 0.0f;
    #pragma unroll 8
    for (int c = 0; c < CQ_; ++c) {
        const float a = __ldcs(up + (size_t)c * HW_);
        const float x = __ldcs(mp + (size_t)c * HW_);
        dot = fmaf(a, x, dot);
        uu  = fmaf(a, a, uu);
        mm  = fmaf(x, x, mm);
    }

    // Combine the four channel-quarters of each position through shared memory.
    __shared__ float s_dot[NQUART_ - 1][POS_PER_BLK_];
    __shared__ float s_uu [NQUART_ - 1][POS_PER_BLK_];
    __shared__ float s_mm [NQUART_ - 1][POS_PER_BLK_];
    __shared__ bool  s_last;

    if (quart != 0) {
        s_dot[quart - 1][pos_in_blk] = dot;
        s_uu [quart - 1][pos_in_blk] = uu;
        s_mm [quart - 1][pos_in_blk] = mm;
    }
    __syncthreads();

    float contrib = 0.0f, msum = 0.0f;
    if (quart == 0) {
        #pragma unroll
        for (int q = 0; q < NQUART_ - 1; ++q) {
            dot += s_dot[q][pos_in_blk];
            uu  += s_uu [q][pos_in_blk];
            mm  += s_mm [q][pos_in_blk];
        }
        const float mf = (__ldg(mask + pos) != 0) ? 1.0f : 0.0f;
        const float denom = fmaxf(sqrtf(uu), EPS_) * fmaxf(sqrtf(mm), EPS_);
        contrib = (dot / denom) * mf;
        msum    = mf;
    }

    // Warp reduction (quart!=0 warps contribute zeros)
    #pragma unroll
    for (int off = 16; off > 0; off >>= 1) {
        contrib += __shfl_down_sync(0xFFFFFFFFu, contrib, off);
        msum    += __shfl_down_sync(0xFFFFFFFFu, msum, off);
    }

    // Block reduction: only warps 0 and 1 (the quart==0 threads) hold nonzero,
    // but reduce across all 8 warps for simplicity.
    __syncthreads();
    const int lane = threadIdx.x & 31;
    const int warp = threadIdx.x >> 5;
    if (lane == 0) { s_dot[0][warp] = contrib; s_uu[0][warp] = msum; }
    __syncthreads();
    if (warp == 0) {
        float bc = (lane < 8) ? s_dot[0][lane] : 0.0f;
        float bm = (lane < 8) ? s_uu[0][lane]  : 0.0f;
        #pragma unroll
        for (int off = 4; off > 0; off >>= 1) {
            bc += __shfl_down_sync(0xFFFFFFFFu, bc, off);
            bm += __shfl_down_sync(0xFFFFFFFFu, bm, off);
        }
        if (lane == 0) {
            atomicAdd(&g_acc[0], bc);
            atomicAdd(&g_acc[1], bm);
            __threadfence();
            const unsigned old = atomicAdd(&g_count, 1u);
            s_last = (old == (unsigned)(gridDim.x - 1));
        }
    }
    __syncthreads();

    // Last block: produce output and reset state for the next replay.
    if (s_last && threadIdx.x == 0) {
        out[0] = g_acc[0] / g_acc[1];
        g_acc[0] = 0.0f;
        g_acc[1] = 0.0f;
        g_count  = 0u;
    }
}

extern "C" void kernel_launch(void* const* d_in, const int* in_sizes, int n_in,
                              void* d_out, int out_size) {
    const float* u    = (const float*)d_in[0];  // unmasked_latent_tensors [B,C,H,W]
    const float* m    = (const float*)d_in[1];  // masked_latent_tensors   [B,C,H,W]
    const int*   mask = (const int*)d_in[2];    // latent_mask [B,H,W]
    float* out = (float*)d_out;

    cms_fused_kernel<<<NBLOCKS_, THREADS_>>>(u, m, mask, out);
}